// round 7
// baseline (speedup 1.0000x reference)
#include <cuda_runtime.h>
#include <cuda_fp16.h>
#include <math.h>
#include <stdint.h>

#define B_    8
#define H_    8
#define LQ_   512
#define T_    8192
#define DIM_  256
#define HD_   32
#define MAXREL_ 128
#define NSPLIT 2
#define TSPLIT (T_ / NSPLIT)
#define NTILES (TSPLIT / 64)

// ---------------- scratch ----------------
__device__ __half g_Qh[B_ * LQ_ * DIM_];
__device__ __half g_KVh[B_ * T_ * 2 * DIM_];
__device__ __half g_em[LQ_ * T_];
__device__ float  g_ctx[B_ * LQ_ * DIM_];
__device__ float  g_op[NSPLIT * B_ * LQ_ * DIM_];        // unnormalized partial O (8 MB)
__device__ float  g_ml[NSPLIT * B_ * LQ_ * H_ * 2];      // per-row (m, l) per split

// ---------------- helpers ----------------
__device__ __forceinline__ void mma_f16(float c[4], const unsigned a[4], unsigned b0, unsigned b1) {
    asm volatile("mma.sync.aligned.m16n8k16.row.col.f32.f16.f16.f32 "
        "{%0,%1,%2,%3}, {%4,%5,%6,%7}, {%8,%9}, {%0,%1,%2,%3};"
        : "+f"(c[0]), "+f"(c[1]), "+f"(c[2]), "+f"(c[3])
        : "r"(a[0]), "r"(a[1]), "r"(a[2]), "r"(a[3]), "r"(b0), "r"(b1));
}
__device__ __forceinline__ unsigned h2u(__half2 h) { return *(unsigned*)&h; }
__device__ __forceinline__ uint32_t smem_u32(const void* p) {
    uint32_t a;
    asm("{ .reg .u64 t; cvta.to.shared.u64 t, %1; cvt.u32.u64 %0, t; }" : "=r"(a) : "l"(p));
    return a;
}
#define LDM_X4(r, addr) \
    asm volatile("ldmatrix.sync.aligned.m8n8.x4.shared.b16 {%0,%1,%2,%3}, [%4];" \
        : "=r"((r)[0]), "=r"((r)[1]), "=r"((r)[2]), "=r"((r)[3]) : "r"(addr))
#define LDM_X4T(r, addr) \
    asm volatile("ldmatrix.sync.aligned.m8n8.x4.trans.shared.b16 {%0,%1,%2,%3}, [%4];" \
        : "=r"((r)[0]), "=r"((r)[1]), "=r"((r)[2]), "=r"((r)[3]) : "r"(addr))
#define CP16(dst, src) \
    asm volatile("cp.async.ca.shared.global [%0], [%1], 16;" :: "r"(dst), "l"(src))
#define CP_COMMIT() asm volatile("cp.async.commit_group;" ::: "memory")

// ---------------- exp(mask) precompute ----------------
__global__ void emask_kernel(const float* __restrict__ rel_bias,
                             const float* __restrict__ mask_scale,
                             __half* __restrict__ em) {
    int idx = blockIdx.x * blockDim.x + threadIdx.x;
    int i = idx >> 13;
    int t = idx & (T_ - 1);
    const float step = 8191.0f / 511.0f;
    float tau = (float)i * step;
    float dt  = (float)t - tau;
    float dtc = fminf(fmaxf(dt, -(float)MAXREL_), (float)MAXREL_);
    int bi = (int)dtc + MAXREL_;
    float bias = rel_bias[bi];
    float z = dt * (1.0f / 64.0f);
    float lg = __logf(__expf(-0.5f * z * z) + 1e-6f);
    em[idx] = __float2half_rn(__expf(mask_scale[0] * (bias + lg)));
}

// ---------------- fp16 GEMM (unchanged from R6, known-good) ----------------
template<bool OHALF>
__global__ void __launch_bounds__(256, 2) gemm16(const float* __restrict__ A,
                                                 const float* __restrict__ W,
                                                 const float* __restrict__ bias,
                                                 void* __restrict__ outp,
                                                 int ldo, float scale) {
    __shared__ __align__(16) unsigned As2[128][20];
    __shared__ __align__(16) unsigned Ws2[128][20];
    int tid = threadIdx.x;
    int lane = tid & 31, warp = tid >> 5;
    int wm = warp >> 1, wn = warp & 1;
    int g = lane >> 2, tig = lane & 3;
    int row0 = blockIdx.x * 128, col0 = blockIdx.y * 128;
    uint32_t sbA = smem_u32(&As2[0][0]);
    uint32_t sbW = smem_u32(&Ws2[0][0]);

    float c[2][8][4];
    #pragma unroll
    for (int i = 0; i < 2; i++)
        #pragma unroll
        for (int j = 0; j < 8; j++)
            #pragma unroll
            for (int v = 0; v < 4; v++) c[i][j][v] = 0.0f;

    int sm  = tid >> 3;
    int sk4 = (tid & 7) * 4;
    uint32_t aArow = (uint32_t)(wm * 32 + (lane & 7) + ((lane >> 3) & 1) * 8);
    uint32_t aAseg = (uint32_t)(lane >> 4);
    uint32_t aBrow = (uint32_t)(wn * 64 + (lane >> 3) * 8 + (lane & 7));

    for (int k0 = 0; k0 < 256; k0 += 32) {
        __syncthreads();
        #pragma unroll
        for (int it = 0; it < 4; it++) {
            int r = sm + it * 32;
            float4 a4 = *(const float4*)&A[(size_t)(row0 + r) * 256 + k0 + sk4];
            float4 w4 = *(const float4*)&W[(size_t)(col0 + r) * 256 + k0 + sk4];
            __half2 a01 = __floats2half2_rn(a4.x, a4.y), a23 = __floats2half2_rn(a4.z, a4.w);
            __half2 w01 = __floats2half2_rn(w4.x, w4.y), w23 = __floats2half2_rn(w4.z, w4.w);
            uint2 ua; ua.x = h2u(a01); ua.y = h2u(a23);
            uint2 uw; uw.x = h2u(w01); uw.y = h2u(w23);
            *(uint2*)&As2[r][sk4 >> 1] = ua;
            *(uint2*)&Ws2[r][sk4 >> 1] = uw;
        }
        __syncthreads();
        #pragma unroll
        for (int kc = 0; kc < 2; kc++) {
            unsigned af0[4], af1[4];
            LDM_X4(af0, sbA + aArow * 80 + (kc * 2 + aAseg) * 16);
            LDM_X4(af1, sbA + (aArow + 16) * 80 + (kc * 2 + aAseg) * 16);
            unsigned b0a[4], b1a[4], b0b[4], b1b[4];
            uint32_t aB = sbW + aBrow * 80 + kc * 32;
            LDM_X4(b0a, aB);
            LDM_X4(b1a, aB + 16);
            LDM_X4(b0b, aB + 32 * 80);
            LDM_X4(b1b, aB + 32 * 80 + 16);
            #pragma unroll
            for (int j = 0; j < 8; j++) {
                unsigned bb0 = (j < 4) ? b0a[j] : b0b[j - 4];
                unsigned bb1 = (j < 4) ? b1a[j] : b1b[j - 4];
                mma_f16(c[0][j], af0, bb0, bb1);
                mma_f16(c[1][j], af1, bb0, bb1);
            }
        }
    }

    #pragma unroll
    for (int j = 0; j < 8; j++) {
        int colg = col0 + wn * 64 + j * 8 + 2 * tig;
        float2 bv = *(const float2*)&bias[colg];
        #pragma unroll
        for (int i = 0; i < 2; i++) {
            int rowg = row0 + wm * 32 + i * 16 + g;
            float x0 = scale * (c[i][j][0] + bv.x);
            float y0 = scale * (c[i][j][1] + bv.y);
            float x1 = scale * (c[i][j][2] + bv.x);
            float y1 = scale * (c[i][j][3] + bv.y);
            if (OHALF) {
                __half* o = (__half*)outp;
                *(unsigned*)&o[(size_t)rowg * ldo + colg] = h2u(__floats2half2_rn(x0, y0));
                *(unsigned*)&o[(size_t)(rowg + 8) * ldo + colg] = h2u(__floats2half2_rn(x1, y1));
            } else {
                float* o = (float*)outp;
                float2 r0; r0.x = x0; r0.y = y0;
                float2 r1; r1.x = x1; r1.y = y1;
                *(float2*)&o[(size_t)rowg * ldo + colg] = r0;
                *(float2*)&o[(size_t)(rowg + 8) * ldo + colg] = r1;
            }
        }
    }
}

// ---------------- flash attention: warp = 16q x 64k, cp.async double buffer, split-T ----------------
// grid (Lq/64, H, B*NSPLIT), 128 threads (4 warps).
__global__ void __launch_bounds__(128, 5) attn16s(const __half* __restrict__ Qh,
                                                  const __half* __restrict__ KVh,
                                                  const __half* __restrict__ emh,
                                                  float* __restrict__ opart,
                                                  float* __restrict__ mlpart) {
    __shared__ __align__(16) unsigned KVbuf[2][2][64][20];   // [stage][K|V][t][d], 80B rows

    int tid = threadIdx.x;
    int lane = tid & 31, warp = tid >> 5;
    int g = lane >> 2, tig = lane & 3;
    int q0 = blockIdx.x * 64, h = blockIdx.y;
    int b = blockIdx.z >> 1, s = blockIdx.z & 1;
    int tb = s * TSPLIT;
    uint32_t sb = smem_u32(&KVbuf[0][0][0][0]);

    int rowq = q0 + warp * 16 + g;                 // rows rowq, rowq+8
    // Q A-frags resident
    unsigned qf[2][4];
    {
        const __half* qb0 = &Qh[(size_t)(b * LQ_ + rowq) * DIM_ + h * HD_ + 2 * tig];
        #pragma unroll
        for (int kc = 0; kc < 2; kc++) {
            const __half* qb = qb0 + kc * 16;
            qf[kc][0] = *(const unsigned*)qb;
            qf[kc][1] = *(const unsigned*)(qb + 8 * DIM_);
            qf[kc][2] = *(const unsigned*)(qb + 8);
            qf[kc][3] = *(const unsigned*)(qb + 8 * DIM_ + 8);
        }
    }

    // staging addresses (4 x 16B per thread per tile: 2 for K, 2 for V)
    int srow0 = tid >> 2, seg = tid & 3;           // rows tid>>2 and +32
    uint32_t dK0 = sb + (uint32_t)(srow0 * 80 + seg * 16);
    uint32_t dK1 = dK0 + 32 * 80;
    const __half* sK0 = &KVh[(size_t)(b * T_ + tb + srow0) * (2 * DIM_) + h * HD_ + seg * 8];

    // fragment lane addresses
    uint32_t kAddr = sb + (uint32_t)(((lane >> 3) * 8 + (lane & 7)) * 80);
    uint32_t vAddr = sb + 5120 + (uint32_t)((lane & 7) * 80 + (lane >> 3) * 16);

    float m[2] = {-1e30f, -1e30f};
    float l[2] = {0.0f, 0.0f};
    float o[4][4];
    #pragma unroll
    for (int n = 0; n < 4; n++)
        #pragma unroll
        for (int v = 0; v < 4; v++) o[n][v] = 0.0f;

    // prologue: stage tile 0 into stage 0
    {
        const __half* p = sK0;
        CP16(dK0, p); CP16(dK1, p + (size_t)32 * 2 * DIM_);
        CP16(dK0 + 5120, p + DIM_); CP16(dK1 + 5120, p + (size_t)32 * 2 * DIM_ + DIM_);
        CP_COMMIT();
    }

    for (int tt = 0; tt < NTILES; tt++) {
        int cur = tt & 1;
        if (tt + 1 < NTILES) {
            uint32_t dst = (uint32_t)((cur ^ 1) * 10240);
            const __half* p = sK0 + (size_t)(tt + 1) * 64 * 2 * DIM_;
            CP16(dK0 + dst, p); CP16(dK1 + dst, p + (size_t)32 * 2 * DIM_);
            CP16(dK0 + dst + 5120, p + DIM_); CP16(dK1 + dst + 5120, p + (size_t)32 * 2 * DIM_ + DIM_);
            CP_COMMIT();
            asm volatile("cp.async.wait_group 1;" ::: "memory");
        } else {
            asm volatile("cp.async.wait_group 0;" ::: "memory");
        }
        __syncthreads();

        uint32_t stoff = (uint32_t)(cur * 10240);

        // S = Q.K^T : 16q x 64k
        float c[8][4];
        #pragma unroll
        for (int j = 0; j < 8; j++)
            #pragma unroll
            for (int v = 0; v < 4; v++) c[j][v] = 0.0f;
        #pragma unroll
        for (int kc = 0; kc < 2; kc++) {
            unsigned kA0[4], kA1[4], kB0[4], kB1[4];
            uint32_t aB = kAddr + stoff + kc * 32;
            LDM_X4(kA0, aB);
            LDM_X4(kA1, aB + 16);
            LDM_X4(kB0, aB + 32 * 80);
            LDM_X4(kB1, aB + 32 * 80 + 16);
            #pragma unroll
            for (int j = 0; j < 4; j++) {
                mma_f16(c[j], qf[kc], kA0[j], kA1[j]);
                mma_f16(c[j + 4], qf[kc], kB0[j], kB1[j]);
            }
        }

        // warp-local online softmax (rows g / g+8; cols across quad)
        float mx0 = fmaxf(c[0][0], c[0][1]);
        float mx1 = fmaxf(c[0][2], c[0][3]);
        #pragma unroll
        for (int j = 1; j < 8; j++) {
            mx0 = fmaxf(mx0, fmaxf(c[j][0], c[j][1]));
            mx1 = fmaxf(mx1, fmaxf(c[j][2], c[j][3]));
        }
        mx0 = fmaxf(mx0, __shfl_xor_sync(0xffffffffu, mx0, 1));
        mx0 = fmaxf(mx0, __shfl_xor_sync(0xffffffffu, mx0, 2));
        mx1 = fmaxf(mx1, __shfl_xor_sync(0xffffffffu, mx1, 1));
        mx1 = fmaxf(mx1, __shfl_xor_sync(0xffffffffu, mx1, 2));
        float mn0 = fmaxf(m[0], mx0), mn1 = fmaxf(m[1], mx1);
        float al0 = __expf(m[0] - mn0), al1 = __expf(m[1] - mn1);
        m[0] = mn0; m[1] = mn1;

        // p = exp(s-m)*emask
        const __half* ea = &emh[(size_t)rowq * T_ + tb + tt * 64 + 2 * tig];
        const __half* eb = ea + (size_t)8 * T_;
        float ps0 = 0.0f, ps1 = 0.0f;
        #pragma unroll
        for (int j = 0; j < 8; j++) {
            float2 ef0 = __half22float2(*(const __half2*)&ea[j * 8]);
            float2 ef1 = __half22float2(*(const __half2*)&eb[j * 8]);
            c[j][0] = __expf(c[j][0] - mn0) * ef0.x;
            c[j][1] = __expf(c[j][1] - mn0) * ef0.y;
            c[j][2] = __expf(c[j][2] - mn1) * ef1.x;
            c[j][3] = __expf(c[j][3] - mn1) * ef1.y;
            ps0 += c[j][0] + c[j][1];
            ps1 += c[j][2] + c[j][3];
        }
        ps0 += __shfl_xor_sync(0xffffffffu, ps0, 1);
        ps0 += __shfl_xor_sync(0xffffffffu, ps0, 2);
        ps1 += __shfl_xor_sync(0xffffffffu, ps1, 1);
        ps1 += __shfl_xor_sync(0xffffffffu, ps1, 2);
        l[0] = l[0] * al0 + ps0;
        l[1] = l[1] * al1 + ps1;

        // pack P into A-frags (registers only)
        unsigned pf[4][4];
        #pragma unroll
        for (int kc2 = 0; kc2 < 4; kc2++) {
            pf[kc2][0] = h2u(__floats2half2_rn(c[2 * kc2][0], c[2 * kc2][1]));
            pf[kc2][1] = h2u(__floats2half2_rn(c[2 * kc2][2], c[2 * kc2][3]));
            pf[kc2][2] = h2u(__floats2half2_rn(c[2 * kc2 + 1][0], c[2 * kc2 + 1][1]));
            pf[kc2][3] = h2u(__floats2half2_rn(c[2 * kc2 + 1][2], c[2 * kc2 + 1][3]));
        }

        // rescale O
        #pragma unroll
        for (int n = 0; n < 4; n++) {
            o[n][0] *= al0; o[n][1] *= al0;
            o[n][2] *= al1; o[n][3] *= al1;
        }

        // O += P.V : 16q x 32d x 64k
        #pragma unroll
        for (int kc2 = 0; kc2 < 4; kc2++) {
            unsigned vb0[4], vb1[4];
            uint32_t aV = vAddr + stoff + kc2 * 16 * 80;
            LDM_X4T(vb0, aV);
            LDM_X4T(vb1, aV + 8 * 80);
            #pragma unroll
            for (int n = 0; n < 4; n++)
                mma_f16(o[n], pf[kc2], vb0[n], vb1[n]);
        }
        __syncthreads();
    }

    // store unnormalized partials + (m, l)
    float* ob = &opart[(size_t)((s * B_ + b) * LQ_ + rowq) * DIM_ + h * HD_ + 2 * tig];
    #pragma unroll
    for (int n = 0; n < 4; n++) {
        float2 w0; w0.x = o[n][0]; w0.y = o[n][1];
        float2 w1; w1.x = o[n][2]; w1.y = o[n][3];
        *(float2*)&ob[n * 8] = w0;
        *(float2*)&ob[(size_t)8 * DIM_ + n * 8] = w1;
    }
    if (tig == 0) {
        float* mlb = &mlpart[(size_t)((s * B_ + b) * LQ_ + rowq) * (H_ * 2) + h * 2];
        mlb[0] = m[0]; mlb[1] = l[0];
        mlb[(size_t)8 * H_ * 2] = m[1]; mlb[(size_t)8 * H_ * 2 + 1] = l[1];
    }
}

// ---------------- split merge ----------------
__global__ void merge_kernel(const float* __restrict__ opart,
                             const float* __restrict__ mlpart,
                             float* __restrict__ ctx) {
    int idx = blockIdx.x * blockDim.x + threadIdx.x;   // over B*LQ*DIM/4
    int row = idx >> 6;                                 // b*LQ + q
    int d4 = (idx & 63) * 4;
    int h = d4 >> 5;
    const float* ml0 = &mlpart[(size_t)row * (H_ * 2) + h * 2];
    const float* ml1 = ml0 + (size_t)B_ * LQ_ * H_ * 2;
    float m0 = ml0[0], l0 = ml0[1], m1 = ml1[0], l1 = ml1[1];
    float M = fmaxf(m0, m1);
    float w0 = __expf(m0 - M), w1 = __expf(m1 - M);
    float inv = 1.0f / (l0 * w0 + l1 * w1);
    float4 a = *(const float4*)&opart[(size_t)row * DIM_ + d4];
    float4 bb = *(const float4*)&opart[(size_t)(B_ * LQ_ + row) * DIM_ + d4];
    float4 r;
    r.x = (a.x * w0 + bb.x * w1) * inv;
    r.y = (a.y * w0 + bb.y * w1) * inv;
    r.z = (a.z * w0 + bb.z * w1) * inv;
    r.w = (a.w * w0 + bb.w * w1) * inv;
    *(float4*)&ctx[(size_t)row * DIM_ + d4] = r;
}

// ---------------- launch ----------------
extern "C" void kernel_launch(void* const* d_in, const int* in_sizes, int n_in,
                              void* d_out, int out_size) {
    const float* q          = (const float*)d_in[0];
    const float* kv         = (const float*)d_in[1];
    const float* in_proj_w  = (const float*)d_in[2];
    const float* in_proj_b  = (const float*)d_in[3];
    const float* out_proj_w = (const float*)d_in[4];
    const float* out_proj_b = (const float*)d_in[5];
    const float* rel_bias   = (const float*)d_in[6];
    const float* mask_scale = (const float*)d_in[7];
    float* out = (float*)d_out;

    __half *pQ, *pKV, *pEM;
    float *pC, *pOP, *pML;
    cudaGetSymbolAddress((void**)&pQ,  g_Qh);
    cudaGetSymbolAddress((void**)&pKV, g_KVh);
    cudaGetSymbolAddress((void**)&pEM, g_em);
    cudaGetSymbolAddress((void**)&pC,  g_ctx);
    cudaGetSymbolAddress((void**)&pOP, g_op);
    cudaGetSymbolAddress((void**)&pML, g_ml);

    const float attn_scale = 0.17677669529663687f;  // 1/sqrt(32)

    emask_kernel<<<(LQ_ * T_) / 256, 256>>>(rel_bias, mask_scale, pEM);

    gemm16<true><<<dim3((B_ * LQ_) / 128, DIM_ / 128), 256>>>(
        q, in_proj_w, in_proj_b, pQ, DIM_, attn_scale);

    gemm16<true><<<dim3((B_ * T_) / 128, (2 * DIM_) / 128), 256>>>(
        kv, in_proj_w + DIM_ * DIM_, in_proj_b + DIM_, pKV, 2 * DIM_, 1.0f);

    attn16s<<<dim3(LQ_ / 64, H_, B_ * NSPLIT), 128>>>(pQ, pKV, pEM, pOP, pML);

    merge_kernel<<<(B_ * LQ_ * DIM_ / 4) / 256, 256>>>(pOP, pML, pC);

    gemm16<false><<<dim3((B_ * LQ_) / 128, DIM_ / 128), 256>>>(
        pC, out_proj_w, out_proj_b, out, DIM_, 1.0f);
}

// round 8
// speedup vs baseline: 1.7321x; 1.7321x over previous
#include <cuda_runtime.h>
#include <cuda_fp16.h>
#include <math.h>
#include <stdint.h>

#define B_    8
#define H_    8
#define LQ_   512
#define T_    8192
#define DIM_  256
#define HD_   32
#define MAXREL_ 128
#define NSPLIT 2
#define TSPLIT (T_ / NSPLIT)
#define NTILES (TSPLIT / 64)

// ---------------- scratch ----------------
__device__ __half g_Qh[B_ * LQ_ * DIM_];
__device__ __half g_KVh[B_ * T_ * 2 * DIM_];
__device__ __half g_em[LQ_ * T_];
__device__ float  g_ctx[B_ * LQ_ * DIM_];
__device__ float  g_op[NSPLIT * B_ * LQ_ * DIM_];
__device__ float  g_ml[NSPLIT * B_ * LQ_ * H_ * 2];

// ---------------- helpers ----------------
__device__ __forceinline__ void mma_f16(float c[4], const unsigned a[4], unsigned b0, unsigned b1) {
    asm volatile("mma.sync.aligned.m16n8k16.row.col.f32.f16.f16.f32 "
        "{%0,%1,%2,%3}, {%4,%5,%6,%7}, {%8,%9}, {%0,%1,%2,%3};"
        : "+f"(c[0]), "+f"(c[1]), "+f"(c[2]), "+f"(c[3])
        : "r"(a[0]), "r"(a[1]), "r"(a[2]), "r"(a[3]), "r"(b0), "r"(b1));
}
__device__ __forceinline__ unsigned h2u(__half2 h) { return *(unsigned*)&h; }
__device__ __forceinline__ uint32_t smem_u32(const void* p) {
    uint32_t a;
    asm("{ .reg .u64 t; cvta.to.shared.u64 t, %1; cvt.u32.u64 %0, t; }" : "=r"(a) : "l"(p));
    return a;
}
__device__ __forceinline__ float ex2(float x) {
    float r; asm("ex2.approx.f32 %0, %1;" : "=f"(r) : "f"(x)); return r;
}
#define LDM_X4(r, addr) \
    asm volatile("ldmatrix.sync.aligned.m8n8.x4.shared.b16 {%0,%1,%2,%3}, [%4];" \
        : "=r"((r)[0]), "=r"((r)[1]), "=r"((r)[2]), "=r"((r)[3]) : "r"(addr))
#define LDM_X4T(r, addr) \
    asm volatile("ldmatrix.sync.aligned.m8n8.x4.trans.shared.b16 {%0,%1,%2,%3}, [%4];" \
        : "=r"((r)[0]), "=r"((r)[1]), "=r"((r)[2]), "=r"((r)[3]) : "r"(addr))
#define CP16(dst, src) \
    asm volatile("cp.async.ca.shared.global [%0], [%1], 16;" :: "r"(dst), "l"(src))
#define CP_COMMIT() asm volatile("cp.async.commit_group;" ::: "memory")
#define CP_WAIT0()  asm volatile("cp.async.wait_group 0;" ::: "memory")

// stage layout inside one buffer: K @0 (64x80B), V @5120 (64x80B), M @10240 (64x144B)
#define STG_SZ 19456
#define OFF_V  5120
#define OFF_M  10240

// ---------------- exp(mask) precompute ----------------
__global__ void emask_kernel(const float* __restrict__ rel_bias,
                             const float* __restrict__ mask_scale,
                             __half* __restrict__ em) {
    int idx = blockIdx.x * blockDim.x + threadIdx.x;
    int i = idx >> 13;
    int t = idx & (T_ - 1);
    const float step = 8191.0f / 511.0f;
    float tau = (float)i * step;
    float dt  = (float)t - tau;
    float dtc = fminf(fmaxf(dt, -(float)MAXREL_), (float)MAXREL_);
    int bi = (int)dtc + MAXREL_;
    float bias = rel_bias[bi];
    float z = dt * (1.0f / 64.0f);
    float lg = __logf(__expf(-0.5f * z * z) + 1e-6f);
    em[idx] = __float2half_rn(__expf(mask_scale[0] * (bias + lg)));
}

// ---------------- fp16 GEMM (known-good from R6) ----------------
template<bool OHALF>
__global__ void __launch_bounds__(256, 2) gemm16(const float* __restrict__ A,
                                                 const float* __restrict__ W,
                                                 const float* __restrict__ bias,
                                                 void* __restrict__ outp,
                                                 int ldo, float scale) {
    __shared__ __align__(16) unsigned As2[128][20];
    __shared__ __align__(16) unsigned Ws2[128][20];
    int tid = threadIdx.x;
    int lane = tid & 31, warp = tid >> 5;
    int wm = warp >> 1, wn = warp & 1;
    int g = lane >> 2, tig = lane & 3;
    int row0 = blockIdx.x * 128, col0 = blockIdx.y * 128;
    uint32_t sbA = smem_u32(&As2[0][0]);
    uint32_t sbW = smem_u32(&Ws2[0][0]);

    float c[2][8][4];
    #pragma unroll
    for (int i = 0; i < 2; i++)
        #pragma unroll
        for (int j = 0; j < 8; j++)
            #pragma unroll
            for (int v = 0; v < 4; v++) c[i][j][v] = 0.0f;

    int sm  = tid >> 3;
    int sk4 = (tid & 7) * 4;
    uint32_t aArow = (uint32_t)(wm * 32 + (lane & 7) + ((lane >> 3) & 1) * 8);
    uint32_t aAseg = (uint32_t)(lane >> 4);
    uint32_t aBrow = (uint32_t)(wn * 64 + (lane >> 3) * 8 + (lane & 7));

    for (int k0 = 0; k0 < 256; k0 += 32) {
        __syncthreads();
        #pragma unroll
        for (int it = 0; it < 4; it++) {
            int r = sm + it * 32;
            float4 a4 = *(const float4*)&A[(size_t)(row0 + r) * 256 + k0 + sk4];
            float4 w4 = *(const float4*)&W[(size_t)(col0 + r) * 256 + k0 + sk4];
            __half2 a01 = __floats2half2_rn(a4.x, a4.y), a23 = __floats2half2_rn(a4.z, a4.w);
            __half2 w01 = __floats2half2_rn(w4.x, w4.y), w23 = __floats2half2_rn(w4.z, w4.w);
            uint2 ua; ua.x = h2u(a01); ua.y = h2u(a23);
            uint2 uw; uw.x = h2u(w01); uw.y = h2u(w23);
            *(uint2*)&As2[r][sk4 >> 1] = ua;
            *(uint2*)&Ws2[r][sk4 >> 1] = uw;
        }
        __syncthreads();
        #pragma unroll
        for (int kc = 0; kc < 2; kc++) {
            unsigned af0[4], af1[4];
            LDM_X4(af0, sbA + aArow * 80 + (kc * 2 + aAseg) * 16);
            LDM_X4(af1, sbA + (aArow + 16) * 80 + (kc * 2 + aAseg) * 16);
            unsigned b0a[4], b1a[4], b0b[4], b1b[4];
            uint32_t aB = sbW + aBrow * 80 + kc * 32;
            LDM_X4(b0a, aB);
            LDM_X4(b1a, aB + 16);
            LDM_X4(b0b, aB + 32 * 80);
            LDM_X4(b1b, aB + 32 * 80 + 16);
            #pragma unroll
            for (int j = 0; j < 8; j++) {
                unsigned bb0 = (j < 4) ? b0a[j] : b0b[j - 4];
                unsigned bb1 = (j < 4) ? b1a[j] : b1b[j - 4];
                mma_f16(c[0][j], af0, bb0, bb1);
                mma_f16(c[1][j], af1, bb0, bb1);
            }
        }
    }

    #pragma unroll
    for (int j = 0; j < 8; j++) {
        int colg = col0 + wn * 64 + j * 8 + 2 * tig;
        float2 bv = *(const float2*)&bias[colg];
        #pragma unroll
        for (int i = 0; i < 2; i++) {
            int rowg = row0 + wm * 32 + i * 16 + g;
            float x0 = scale * (c[i][j][0] + bv.x);
            float y0 = scale * (c[i][j][1] + bv.y);
            float x1 = scale * (c[i][j][2] + bv.x);
            float y1 = scale * (c[i][j][3] + bv.y);
            if (OHALF) {
                __half* o = (__half*)outp;
                *(unsigned*)&o[(size_t)rowg * ldo + colg] = h2u(__floats2half2_rn(x0, y0));
                *(unsigned*)&o[(size_t)(rowg + 8) * ldo + colg] = h2u(__floats2half2_rn(x1, y1));
            } else {
                float* o = (float*)outp;
                float2 r0; r0.x = x0; r0.y = y0;
                float2 r1; r1.x = x1; r1.y = y1;
                *(float2*)&o[(size_t)rowg * ldo + colg] = r0;
                *(float2*)&o[(size_t)(rowg + 8) * ldo + colg] = r1;
            }
        }
    }
}

// ---------------- flash attention: R6 layout + cp.async pipeline + smem mask + split-T ----------------
// grid (Lq/64, H, B*NSPLIT), 128 threads (4 warps). warp = (qg, kh): 32q x 32k-half.
// Q pre-scaled by log2(e)/sqrt(HD): scores in log2 domain, ex2 for softmax.
__global__ void __launch_bounds__(128, 4) attn16(const __half* __restrict__ Qh,
                                                 const __half* __restrict__ KVh,
                                                 const __half* __restrict__ emh,
                                                 float* __restrict__ opart,
                                                 float* __restrict__ mlpart) {
    __shared__ __align__(16) char KVM[2][STG_SZ];
    __shared__ float redm[2][64];
    __shared__ float redl[2][64];

    int tid = threadIdx.x;
    int lane = tid & 31, warp = tid >> 5;
    int qg = warp >> 1, kh = warp & 1;
    int g = lane >> 2, tig = lane & 3;
    int q0 = blockIdx.x * 64, h = blockIdx.y;
    int b = blockIdx.z >> 1, s = blockIdx.z & 1;
    int tb = s * TSPLIT;
    uint32_t sb = smem_u32(&KVM[0][0]);

    // Q A-frags resident
    unsigned qf[2][2][4];
    #pragma unroll
    for (int mfr = 0; mfr < 2; mfr++) {
        const __half* qb0 = &Qh[(size_t)(b * LQ_ + q0 + qg * 32 + mfr * 16 + g) * DIM_ + h * HD_ + 2 * tig];
        #pragma unroll
        for (int kc = 0; kc < 2; kc++) {
            const __half* qb = qb0 + kc * 16;
            qf[mfr][kc][0] = *(const unsigned*)qb;
            qf[mfr][kc][1] = *(const unsigned*)(qb + 8 * DIM_);
            qf[mfr][kc][2] = *(const unsigned*)(qb + 8);
            qf[mfr][kc][3] = *(const unsigned*)(qb + 8 * DIM_ + 8);
        }
    }

    // staging addresses
    int srow = tid >> 2, seg = tid & 3;             // K/V: rows srow, srow+32
    uint32_t dK0 = sb + (uint32_t)(srow * 80 + seg * 16);
    uint32_t dK1 = dK0 + 32 * 80;
    const __half* sKV = &KVh[(size_t)(b * T_ + tb + srow) * (2 * DIM_) + h * HD_ + seg * 8];
    int mrow = tid >> 1, mseg = (tid & 1) * 64;     // M: row mrow, 64B half-row
    uint32_t dM = sb + OFF_M + (uint32_t)(mrow * 144 + mseg);
    const __half* sM = &emh[(size_t)(q0 + mrow) * T_ + tb + mseg / 2];

    // fragment lane addresses
    uint32_t kAddr = (uint32_t)((kh * 32 + (lane >> 3) * 8 + (lane & 7)) * 80);
    uint32_t vAddr = (uint32_t)(OFF_V + (kh * 32 + (lane & 7)) * 80 + (lane >> 3) * 16);
    uint32_t mAddrB = (uint32_t)(OFF_M + (qg * 32 + (lane & 15)) * 144 + kh * 64 + (lane >> 4) * 16);

    float m[2][2], l[2][2], o[2][4][4];
    #pragma unroll
    for (int i = 0; i < 2; i++)
        #pragma unroll
        for (int j = 0; j < 2; j++) { m[i][j] = -1e30f; l[i][j] = 0.0f; }
    #pragma unroll
    for (int i = 0; i < 2; i++)
        #pragma unroll
        for (int n = 0; n < 4; n++)
            #pragma unroll
            for (int v = 0; v < 4; v++) o[i][n][v] = 0.0f;

    // prologue: stage tile 0 into buffer 0
    {
        const __half* p = sKV;
        CP16(dK0, p); CP16(dK1, p + (size_t)32 * 2 * DIM_);
        CP16(dK0 + OFF_V, p + DIM_); CP16(dK1 + OFF_V, p + (size_t)32 * 2 * DIM_ + DIM_);
        const __half* pm = sM;
        CP16(dM, pm); CP16(dM + 16, pm + 8); CP16(dM + 32, pm + 16); CP16(dM + 48, pm + 24);
        CP_COMMIT();
    }

    for (int tt = 0; tt < NTILES; tt++) {
        uint32_t stoff = (uint32_t)((tt & 1) * STG_SZ);
        CP_WAIT0();
        __syncthreads();                 // tile tt staged; prev redl visible

        if (tt != 0) {
            #pragma unroll
            for (int mfr = 0; mfr < 2; mfr++)
                #pragma unroll
                for (int hi = 0; hi < 2; hi++) {
                    int lr = qg * 32 + mfr * 16 + hi * 8 + g;
                    l[mfr][hi] += redl[0][lr] + redl[1][lr];
                }
        }

        // S = Q.K^T (32q x 32k per warp)
        float c[2][4][4];
        #pragma unroll
        for (int mfr = 0; mfr < 2; mfr++)
            #pragma unroll
            for (int j = 0; j < 4; j++)
                #pragma unroll
                for (int v = 0; v < 4; v++) c[mfr][j][v] = 0.0f;
        #pragma unroll
        for (int kc = 0; kc < 2; kc++) {
            unsigned kb0[4], kb1[4];
            uint32_t aB = sb + stoff + kAddr + kc * 32;
            LDM_X4(kb0, aB);
            LDM_X4(kb1, aB + 16);
            #pragma unroll
            for (int j = 0; j < 4; j++) {
                mma_f16(c[0][j], qf[0][kc], kb0[j], kb1[j]);
                mma_f16(c[1][j], qf[1][kc], kb0[j], kb1[j]);
            }
        }

        // row max (own 32 cols), exchange across kh
        #pragma unroll
        for (int mfr = 0; mfr < 2; mfr++)
            #pragma unroll
            for (int hi = 0; hi < 2; hi++) {
                float mx = c[mfr][0][hi * 2];
                #pragma unroll
                for (int j = 0; j < 4; j++)
                    mx = fmaxf(mx, fmaxf(c[mfr][j][hi * 2], c[mfr][j][hi * 2 + 1]));
                mx = fmaxf(mx, __shfl_xor_sync(0xffffffffu, mx, 1));
                mx = fmaxf(mx, __shfl_xor_sync(0xffffffffu, mx, 2));
                if (tig == 0) redm[kh][qg * 32 + mfr * 16 + hi * 8 + g] = mx;
            }
        __syncthreads();

        // prefetch tile tt+1 into the other buffer (safe: last read 2 tiles ago)
        if (tt + 1 < NTILES) {
            uint32_t dst = (uint32_t)(((tt & 1) ^ 1) * STG_SZ);
            const __half* p = sKV + (size_t)(tt + 1) * 64 * 2 * DIM_;
            CP16(dK0 + dst, p); CP16(dK1 + dst, p + (size_t)32 * 2 * DIM_);
            CP16(dK0 + dst + OFF_V, p + DIM_); CP16(dK1 + dst + OFF_V, p + (size_t)32 * 2 * DIM_ + DIM_);
            const __half* pm = sM + (size_t)(tt + 1) * 64;
            uint32_t dMd = dM + dst;
            CP16(dMd, pm); CP16(dMd + 16, pm + 8); CP16(dMd + 32, pm + 16); CP16(dMd + 48, pm + 24);
            CP_COMMIT();
        }

        float al[2][2], psum[2][2];
        #pragma unroll
        for (int mfr = 0; mfr < 2; mfr++)
            #pragma unroll
            for (int hi = 0; hi < 2; hi++) {
                int lr = qg * 32 + mfr * 16 + hi * 8 + g;
                float mn = fmaxf(m[mfr][hi], fmaxf(redm[0][lr], redm[1][lr]));
                al[mfr][hi] = ex2(m[mfr][hi] - mn);
                m[mfr][hi] = mn;
                l[mfr][hi] *= al[mfr][hi];
                psum[mfr][hi] = 0.0f;
            }

        // p = ex2(s-m) * emask (mask frags via ldmatrix from smem)
        unsigned pf[2][2][4];
        #pragma unroll
        for (int mfr = 0; mfr < 2; mfr++) {
            unsigned me0[4], me1[4];
            uint32_t aM = sb + stoff + mAddrB + (uint32_t)(mfr * 16 * 144);
            LDM_X4(me0, aM);          // cols kh*32 + 0..15  (j = 0, 1)
            LDM_X4(me1, aM + 32);     // cols kh*32 + 16..31 (j = 2, 3)
            #pragma unroll
            for (int j = 0; j < 4; j++) {
                unsigned eg  = (j < 2) ? me0[(j & 1) * 2]     : me1[(j & 1) * 2];
                unsigned eg8 = (j < 2) ? me0[(j & 1) * 2 + 1] : me1[(j & 1) * 2 + 1];
                float2 ef0 = __half22float2(*(__half2*)&eg);
                float2 ef1 = __half22float2(*(__half2*)&eg8);
                float p0 = ex2(c[mfr][j][0] - m[mfr][0]) * ef0.x;
                float p1 = ex2(c[mfr][j][1] - m[mfr][0]) * ef0.y;
                float p2 = ex2(c[mfr][j][2] - m[mfr][1]) * ef1.x;
                float p3 = ex2(c[mfr][j][3] - m[mfr][1]) * ef1.y;
                psum[mfr][0] += p0 + p1;
                psum[mfr][1] += p2 + p3;
                pf[mfr][j >> 1][(j & 1) * 2 + 0] = h2u(__floats2half2_rn(p0, p1));
                pf[mfr][j >> 1][(j & 1) * 2 + 1] = h2u(__floats2half2_rn(p2, p3));
            }
        }
        #pragma unroll
        for (int mfr = 0; mfr < 2; mfr++)
            #pragma unroll
            for (int hi = 0; hi < 2; hi++) {
                float ps = psum[mfr][hi];
                ps += __shfl_xor_sync(0xffffffffu, ps, 1);
                ps += __shfl_xor_sync(0xffffffffu, ps, 2);
                if (tig == 0) redl[kh][qg * 32 + mfr * 16 + hi * 8 + g] = ps;
            }

        // rescale O
        #pragma unroll
        for (int mfr = 0; mfr < 2; mfr++)
            #pragma unroll
            for (int n = 0; n < 4; n++) {
                o[mfr][n][0] *= al[mfr][0]; o[mfr][n][1] *= al[mfr][0];
                o[mfr][n][2] *= al[mfr][1]; o[mfr][n][3] *= al[mfr][1];
            }

        // O += P.V over own key half
        #pragma unroll
        for (int kc = 0; kc < 2; kc++) {
            unsigned vb0[4], vb1[4];
            uint32_t aV = sb + stoff + vAddr + (uint32_t)(kc * 16 * 80);
            LDM_X4T(vb0, aV);
            LDM_X4T(vb1, aV + 8 * 80);
            #pragma unroll
            for (int n = 0; n < 4; n++) {
                mma_f16(o[0][n], pf[0][kc], vb0[n], vb1[n]);
                mma_f16(o[1][n], pf[1][kc], vb0[n], vb1[n]);
            }
        }
    }

    __syncthreads();                    // last redl visible; buffers free
    #pragma unroll
    for (int mfr = 0; mfr < 2; mfr++)
        #pragma unroll
        for (int hi = 0; hi < 2; hi++) {
            int lr = qg * 32 + mfr * 16 + hi * 8 + g;
            l[mfr][hi] += redl[0][lr] + redl[1][lr];
        }

    // combine kh partials (unnormalized) via smem alias; store partial O + (m, l)
    float* Os = (float*)&KVM[0][0];
    if (kh == 1) {
        #pragma unroll
        for (int mfr = 0; mfr < 2; mfr++)
            #pragma unroll
            for (int n = 0; n < 4; n++) {
                int base0 = qg * 1088 + (mfr * 16 + g) * 34 + n * 8 + 2 * tig;
                int base1 = base0 + 8 * 34;
                float2 w0; w0.x = o[mfr][n][0]; w0.y = o[mfr][n][1];
                float2 w1; w1.x = o[mfr][n][2]; w1.y = o[mfr][n][3];
                *(float2*)&Os[base0] = w0;
                *(float2*)&Os[base1] = w1;
            }
    }
    __syncthreads();
    if (kh == 0) {
        #pragma unroll
        for (int mfr = 0; mfr < 2; mfr++) {
            #pragma unroll
            for (int n = 0; n < 4; n++) {
                int base0 = qg * 1088 + (mfr * 16 + g) * 34 + n * 8 + 2 * tig;
                int base1 = base0 + 8 * 34;
                float2 p0 = *(float2*)&Os[base0];
                float2 p1 = *(float2*)&Os[base1];
                float2 w0, w1;
                w0.x = o[mfr][n][0] + p0.x;
                w0.y = o[mfr][n][1] + p0.y;
                w1.x = o[mfr][n][2] + p1.x;
                w1.y = o[mfr][n][3] + p1.y;
                int r0 = (s * B_ + b) * LQ_ + q0 + qg * 32 + mfr * 16 + g;
                int col = h * HD_ + n * 8 + 2 * tig;
                *(float2*)&opart[(size_t)r0 * DIM_ + col] = w0;
                *(float2*)&opart[(size_t)(r0 + 8) * DIM_ + col] = w1;
            }
        }
        if (tig == 0) {
            #pragma unroll
            for (int mfr = 0; mfr < 2; mfr++)
                #pragma unroll
                for (int hi = 0; hi < 2; hi++) {
                    int rg = (s * B_ + b) * LQ_ + q0 + qg * 32 + mfr * 16 + hi * 8 + g;
                    float* mlb = &mlpart[(size_t)rg * (H_ * 2) + h * 2];
                    mlb[0] = m[mfr][hi];
                    mlb[1] = l[mfr][hi];
                }
        }
    }
}

// ---------------- split merge (m in log2 units) ----------------
__global__ void merge_kernel(const float* __restrict__ opart,
                             const float* __restrict__ mlpart,
                             float* __restrict__ ctx) {
    int idx = blockIdx.x * blockDim.x + threadIdx.x;
    int row = idx >> 6;
    int d4 = (idx & 63) * 4;
    int h = d4 >> 5;
    const float* ml0 = &mlpart[(size_t)row * (H_ * 2) + h * 2];
    const float* ml1 = ml0 + (size_t)B_ * LQ_ * H_ * 2;
    float m0 = ml0[0], l0 = ml0[1], m1 = ml1[0], l1 = ml1[1];
    float M = fmaxf(m0, m1);
    float w0 = ex2(m0 - M), w1 = ex2(m1 - M);
    float inv = 1.0f / (l0 * w0 + l1 * w1);
    float4 a = *(const float4*)&opart[(size_t)row * DIM_ + d4];
    float4 bb = *(const float4*)&opart[(size_t)(B_ * LQ_ + row) * DIM_ + d4];
    float4 r;
    r.x = (a.x * w0 + bb.x * w1) * inv;
    r.y = (a.y * w0 + bb.y * w1) * inv;
    r.z = (a.z * w0 + bb.z * w1) * inv;
    r.w = (a.w * w0 + bb.w * w1) * inv;
    *(float4*)&ctx[(size_t)row * DIM_ + d4] = r;
}

// ---------------- launch ----------------
extern "C" void kernel_launch(void* const* d_in, const int* in_sizes, int n_in,
                              void* d_out, int out_size) {
    const float* q          = (const float*)d_in[0];
    const float* kv         = (const float*)d_in[1];
    const float* in_proj_w  = (const float*)d_in[2];
    const float* in_proj_b  = (const float*)d_in[3];
    const float* out_proj_w = (const float*)d_in[4];
    const float* out_proj_b = (const float*)d_in[5];
    const float* rel_bias   = (const float*)d_in[6];
    const float* mask_scale = (const float*)d_in[7];
    float* out = (float*)d_out;

    __half *pQ, *pKV, *pEM;
    float *pC, *pOP, *pML;
    cudaGetSymbolAddress((void**)&pQ,  g_Qh);
    cudaGetSymbolAddress((void**)&pKV, g_KVh);
    cudaGetSymbolAddress((void**)&pEM, g_em);
    cudaGetSymbolAddress((void**)&pC,  g_ctx);
    cudaGetSymbolAddress((void**)&pOP, g_op);
    cudaGetSymbolAddress((void**)&pML, g_ml);

    // 1/sqrt(32) * log2(e): scores come out in log2 domain
    const float attn_scale = 0.17677669529663687f * 1.4426950408889634f;

    emask_kernel<<<(LQ_ * T_) / 256, 256>>>(rel_bias, mask_scale, pEM);

    gemm16<true><<<dim3((B_ * LQ_) / 128, DIM_ / 128), 256>>>(
        q, in_proj_w, in_proj_b, pQ, DIM_, attn_scale);

    gemm16<true><<<dim3((B_ * T_) / 128, (2 * DIM_) / 128), 256>>>(
        kv, in_proj_w + DIM_ * DIM_, in_proj_b + DIM_, pKV, 2 * DIM_, 1.0f);

    attn16<<<dim3(LQ_ / 64, H_, B_ * NSPLIT), 128>>>(pQ, pKV, pEM, pOP, pML);

    merge_kernel<<<(B_ * LQ_ * DIM_ / 4) / 256, 256>>>(pOP, pML, pC);

    gemm16<false><<<dim3((B_ * LQ_) / 128, DIM_ / 128), 256>>>(
        pC, out_proj_w, out_proj_b, out, DIM_, 1.0f);
}

// round 10
// speedup vs baseline: 1.9739x; 1.1396x over previous
#include <cuda_runtime.h>
#include <cuda_fp16.h>
#include <math.h>
#include <stdint.h>

#define B_    8
#define H_    8
#define LQ_   512
#define T_    8192
#define DIM_  256
#define HD_   32
#define MAXREL_ 128
#define NSPLIT 2
#define TSPLIT (T_ / NSPLIT)
#define NTILES (TSPLIT / 64)
#define STEPF (8191.0f / 511.0f)

// ---------------- scratch ----------------
__device__ __half g_Qh[B_ * LQ_ * DIM_];
__device__ __half g_KVh[B_ * T_ * 2 * DIM_];
__device__ __half g_em[LQ_ * T_];
__device__ float  g_ctx[B_ * LQ_ * DIM_];
__device__ float  g_op[NSPLIT * B_ * LQ_ * DIM_];
__device__ float  g_ml[NSPLIT * B_ * LQ_ * H_ * 2];
__device__ float  g_far[2];          // log2(emask) constants: far-left, far-right

// ---------------- helpers ----------------
__device__ __forceinline__ void mma_f16(float c[4], const unsigned a[4], unsigned b0, unsigned b1) {
    asm volatile("mma.sync.aligned.m16n8k16.row.col.f32.f16.f16.f32 "
        "{%0,%1,%2,%3}, {%4,%5,%6,%7}, {%8,%9}, {%0,%1,%2,%3};"
        : "+f"(c[0]), "+f"(c[1]), "+f"(c[2]), "+f"(c[3])
        : "r"(a[0]), "r"(a[1]), "r"(a[2]), "r"(a[3]), "r"(b0), "r"(b1));
}
__device__ __forceinline__ unsigned h2u(__half2 h) { return *(unsigned*)&h; }
__device__ __forceinline__ uint32_t smem_u32(const void* p) {
    uint32_t a;
    asm("{ .reg .u64 t; cvta.to.shared.u64 t, %1; cvt.u32.u64 %0, t; }" : "=r"(a) : "l"(p));
    return a;
}
__device__ __forceinline__ float ex2(float x) {
    float r; asm("ex2.approx.f32 %0, %1;" : "=f"(r) : "f"(x)); return r;
}
#define LDM_X4(r, addr) \
    asm volatile("ldmatrix.sync.aligned.m8n8.x4.shared.b16 {%0,%1,%2,%3}, [%4];" \
        : "=r"((r)[0]), "=r"((r)[1]), "=r"((r)[2]), "=r"((r)[3]) : "r"(addr))
#define LDM_X4T(r, addr) \
    asm volatile("ldmatrix.sync.aligned.m8n8.x4.trans.shared.b16 {%0,%1,%2,%3}, [%4];" \
        : "=r"((r)[0]), "=r"((r)[1]), "=r"((r)[2]), "=r"((r)[3]) : "r"(addr))
#define CP16(dst, src) \
    asm volatile("cp.async.ca.shared.global [%0], [%1], 16;" :: "r"(dst), "l"(src))
#define CP_COMMIT() asm volatile("cp.async.commit_group;" ::: "memory")
#define CP_WAIT0()  asm volatile("cp.async.wait_group 0;" ::: "memory")

// stage layout inside one buffer: K @0 (64x80B), V @5120 (64x80B), M @10240 (64x144B)
#define STG_SZ 19456
#define OFF_V  5120
#define OFF_M  10240

// ---------------- exp(mask) precompute + far constants ----------------
__global__ void emask_kernel(const float* __restrict__ rel_bias,
                             const float* __restrict__ mask_scale,
                             __half* __restrict__ em,
                             float* __restrict__ farc) {
    int idx = blockIdx.x * blockDim.x + threadIdx.x;
    int i = idx >> 13;
    int t = idx & (T_ - 1);
    float tau = (float)i * STEPF;
    float dt  = (float)t - tau;
    float dtc = fminf(fmaxf(dt, -(float)MAXREL_), (float)MAXREL_);
    int bi = (int)dtc + MAXREL_;
    float bias = rel_bias[bi];
    float z = dt * (1.0f / 64.0f);
    float lg = __logf(__expf(-0.5f * z * z) + 1e-6f);
    em[idx] = __float2half_rn(__expf(mask_scale[0] * (bias + lg)));
    if (idx == 0) {
        const float L2E = 1.4426950408889634f;
        float ms = mask_scale[0];
        farc[0] = ms * (rel_bias[0] + __logf(1e-6f)) * L2E;
        farc[1] = ms * (rel_bias[2 * MAXREL_] + __logf(1e-6f)) * L2E;
    }
}

// ---------------- fp16 GEMM (known-good) ----------------
template<bool OHALF>
__global__ void __launch_bounds__(256, 2) gemm16(const float* __restrict__ A,
                                                 const float* __restrict__ W,
                                                 const float* __restrict__ bias,
                                                 void* __restrict__ outp,
                                                 int ldo, float scale) {
    __shared__ __align__(16) unsigned As2[128][20];
    __shared__ __align__(16) unsigned Ws2[128][20];
    int tid = threadIdx.x;
    int lane = tid & 31, warp = tid >> 5;
    int wm = warp >> 1, wn = warp & 1;
    int g = lane >> 2, tig = lane & 3;
    int row0 = blockIdx.x * 128, col0 = blockIdx.y * 128;
    uint32_t sbA = smem_u32(&As2[0][0]);
    uint32_t sbW = smem_u32(&Ws2[0][0]);

    float c[2][8][4];
    #pragma unroll
    for (int i = 0; i < 2; i++)
        #pragma unroll
        for (int j = 0; j < 8; j++)
            #pragma unroll
            for (int v = 0; v < 4; v++) c[i][j][v] = 0.0f;

    int sm  = tid >> 3;
    int sk4 = (tid & 7) * 4;
    uint32_t aArow = (uint32_t)(wm * 32 + (lane & 7) + ((lane >> 3) & 1) * 8);
    uint32_t aAseg = (uint32_t)(lane >> 4);
    uint32_t aBrow = (uint32_t)(wn * 64 + (lane >> 3) * 8 + (lane & 7));

    for (int k0 = 0; k0 < 256; k0 += 32) {
        __syncthreads();
        #pragma unroll
        for (int it = 0; it < 4; it++) {
            int r = sm + it * 32;
            float4 a4 = *(const float4*)&A[(size_t)(row0 + r) * 256 + k0 + sk4];
            float4 w4 = *(const float4*)&W[(size_t)(col0 + r) * 256 + k0 + sk4];
            __half2 a01 = __floats2half2_rn(a4.x, a4.y), a23 = __floats2half2_rn(a4.z, a4.w);
            __half2 w01 = __floats2half2_rn(w4.x, w4.y), w23 = __floats2half2_rn(w4.z, w4.w);
            uint2 ua; ua.x = h2u(a01); ua.y = h2u(a23);
            uint2 uw; uw.x = h2u(w01); uw.y = h2u(w23);
            *(uint2*)&As2[r][sk4 >> 1] = ua;
            *(uint2*)&Ws2[r][sk4 >> 1] = uw;
        }
        __syncthreads();
        #pragma unroll
        for (int kc = 0; kc < 2; kc++) {
            unsigned af0[4], af1[4];
            LDM_X4(af0, sbA + aArow * 80 + (kc * 2 + aAseg) * 16);
            LDM_X4(af1, sbA + (aArow + 16) * 80 + (kc * 2 + aAseg) * 16);
            unsigned b0a[4], b1a[4], b0b[4], b1b[4];
            uint32_t aB = sbW + aBrow * 80 + kc * 32;
            LDM_X4(b0a, aB);
            LDM_X4(b1a, aB + 16);
            LDM_X4(b0b, aB + 32 * 80);
            LDM_X4(b1b, aB + 32 * 80 + 16);
            #pragma unroll
            for (int j = 0; j < 8; j++) {
                unsigned bb0 = (j < 4) ? b0a[j] : b0b[j - 4];
                unsigned bb1 = (j < 4) ? b1a[j] : b1b[j - 4];
                mma_f16(c[0][j], af0, bb0, bb1);
                mma_f16(c[1][j], af1, bb0, bb1);
            }
        }
    }

    #pragma unroll
    for (int j = 0; j < 8; j++) {
        int colg = col0 + wn * 64 + j * 8 + 2 * tig;
        float2 bv = *(const float2*)&bias[colg];
        #pragma unroll
        for (int i = 0; i < 2; i++) {
            int rowg = row0 + wm * 32 + i * 16 + g;
            float x0 = scale * (c[i][j][0] + bv.x);
            float y0 = scale * (c[i][j][1] + bv.y);
            float x1 = scale * (c[i][j][2] + bv.x);
            float y1 = scale * (c[i][j][3] + bv.y);
            if (OHALF) {
                __half* o = (__half*)outp;
                *(unsigned*)&o[(size_t)rowg * ldo + colg] = h2u(__floats2half2_rn(x0, y0));
                *(unsigned*)&o[(size_t)(rowg + 8) * ldo + colg] = h2u(__floats2half2_rn(x1, y1));
            } else {
                float* o = (float*)outp;
                float2 r0; r0.x = x0; r0.y = y0;
                float2 r1; r1.x = x1; r1.y = y1;
                *(float2*)&o[(size_t)rowg * ldo + colg] = r0;
                *(float2*)&o[(size_t)(rowg + 8) * ldo + colg] = r1;
            }
        }
    }
}

// ---------------- flash attention: far-tile mask fold + ones-column row sums ----------------
// grid (Lq/64, H, B*NSPLIT), 128 threads (4 warps). warp = (qg, kh): 32q x 32k-half.
__global__ void __launch_bounds__(128, 4) attn16(const __half* __restrict__ Qh,
                                                 const __half* __restrict__ KVh,
                                                 const __half* __restrict__ emh,
                                                 const float* __restrict__ farc,
                                                 float* __restrict__ opart,
                                                 float* __restrict__ mlpart) {
    __shared__ __align__(16) char KVM[2][STG_SZ];
    __shared__ float redm[2][64];

    int tid = threadIdx.x;
    int lane = tid & 31, warp = tid >> 5;
    int qg = warp >> 1, kh = warp & 1;
    int g = lane >> 2, tig = lane & 3;
    int q0 = blockIdx.x * 64, h = blockIdx.y;
    int b = blockIdx.z >> 1, s = blockIdx.z & 1;
    int tb = s * TSPLIT;
    uint32_t sb = smem_u32(&KVM[0][0]);

    // far/mixed tile band
    float tauMin = (float)q0 * STEPF;
    float tauMax = (float)(q0 + 63) * STEPF;
    int ttA = (int)floorf((tauMin - 448.0f - 63.0f - (float)tb) * (1.0f / 64.0f)) + 1;
    int ttB = (int)ceilf((tauMax + 448.0f - (float)tb) * (1.0f / 64.0f));
    ttA = max(0, min(NTILES, ttA));
    ttB = max(ttA, min(NTILES, ttB));
    float fL = farc[0], fR = farc[1];

    // Q A-frags resident
    unsigned qf[2][2][4];
    #pragma unroll
    for (int mfr = 0; mfr < 2; mfr++) {
        const __half* qb0 = &Qh[(size_t)(b * LQ_ + q0 + qg * 32 + mfr * 16 + g) * DIM_ + h * HD_ + 2 * tig];
        #pragma unroll
        for (int kc = 0; kc < 2; kc++) {
            const __half* qb = qb0 + kc * 16;
            qf[mfr][kc][0] = *(const unsigned*)qb;
            qf[mfr][kc][1] = *(const unsigned*)(qb + 8 * DIM_);
            qf[mfr][kc][2] = *(const unsigned*)(qb + 8);
            qf[mfr][kc][3] = *(const unsigned*)(qb + 8 * DIM_ + 8);
        }
    }

    // staging addresses
    int srow = tid >> 2, seg = tid & 3;
    uint32_t dK0 = sb + (uint32_t)(srow * 80 + seg * 16);
    uint32_t dK1 = dK0 + 32 * 80;
    const __half* sKV = &KVh[(size_t)(b * T_ + tb + srow) * (2 * DIM_) + h * HD_ + seg * 8];
    int mrow = tid >> 1, mseg = (tid & 1) * 64;
    uint32_t dM = sb + OFF_M + (uint32_t)(mrow * 144 + mseg);
    const __half* sM = &emh[(size_t)(q0 + mrow) * T_ + tb + mseg / 2];

    // fragment lane addresses
    uint32_t kAddr = (uint32_t)((kh * 32 + (lane >> 3) * 8 + (lane & 7)) * 80);
    uint32_t vAddr = (uint32_t)(OFF_V + (kh * 32 + (lane & 7)) * 80 + (lane >> 3) * 16);
    uint32_t mAddrB = (uint32_t)(OFF_M + (qg * 32 + (lane & 15)) * 144 + kh * 64 + (lane >> 4) * 16);

    // ones-column B fragment (V_ext[t][32]=1): constant, no smem
    unsigned bbone = (g == 0) ? 0x3C003C00u : 0u;

    float m[2][2], o[2][5][4];
    #pragma unroll
    for (int i = 0; i < 2; i++)
        #pragma unroll
        for (int j = 0; j < 2; j++) m[i][j] = -1e30f;
    #pragma unroll
    for (int i = 0; i < 2; i++)
        #pragma unroll
        for (int n = 0; n < 5; n++)
            #pragma unroll
            for (int v = 0; v < 4; v++) o[i][n][v] = 0.0f;

    // prologue: stage tile 0 into buffer 0
    {
        const __half* p = sKV;
        CP16(dK0, p); CP16(dK1, p + (size_t)32 * 2 * DIM_);
        CP16(dK0 + OFF_V, p + DIM_); CP16(dK1 + OFF_V, p + (size_t)32 * 2 * DIM_ + DIM_);
        if (0 >= ttA && 0 < ttB) {
            const __half* pm = sM;
            CP16(dM, pm); CP16(dM + 16, pm + 8); CP16(dM + 32, pm + 16); CP16(dM + 48, pm + 24);
        }
        CP_COMMIT();
    }

    for (int tt = 0; tt < NTILES; tt++) {
        uint32_t stoff = (uint32_t)((tt & 1) * STG_SZ);
        bool mixed = (tt >= ttA) && (tt < ttB);
        CP_WAIT0();
        __syncthreads();

        // S = Q.K^T (32q x 32k per warp)
        float c[2][4][4];
        #pragma unroll
        for (int mfr = 0; mfr < 2; mfr++)
            #pragma unroll
            for (int j = 0; j < 4; j++)
                #pragma unroll
                for (int v = 0; v < 4; v++) c[mfr][j][v] = 0.0f;
        #pragma unroll
        for (int kc = 0; kc < 2; kc++) {
            unsigned kb0[4], kb1[4];
            uint32_t aB = sb + stoff + kAddr + kc * 32;
            LDM_X4(kb0, aB);
            LDM_X4(kb1, aB + 16);
            #pragma unroll
            for (int j = 0; j < 4; j++) {
                mma_f16(c[0][j], qf[0][kc], kb0[j], kb1[j]);
                mma_f16(c[1][j], qf[1][kc], kb0[j], kb1[j]);
            }
        }

        // row max, exchanged across kh
        #pragma unroll
        for (int mfr = 0; mfr < 2; mfr++)
            #pragma unroll
            for (int hi = 0; hi < 2; hi++) {
                float mx = c[mfr][0][hi * 2];
                #pragma unroll
                for (int j = 0; j < 4; j++)
                    mx = fmaxf(mx, fmaxf(c[mfr][j][hi * 2], c[mfr][j][hi * 2 + 1]));
                mx = fmaxf(mx, __shfl_xor_sync(0xffffffffu, mx, 1));
                mx = fmaxf(mx, __shfl_xor_sync(0xffffffffu, mx, 2));
                if (tig == 0) redm[kh][qg * 32 + mfr * 16 + hi * 8 + g] = mx;
            }
        __syncthreads();

        // prefetch tile tt+1
        if (tt + 1 < NTILES) {
            uint32_t dst = (uint32_t)(((tt & 1) ^ 1) * STG_SZ);
            const __half* p = sKV + (size_t)(tt + 1) * 64 * 2 * DIM_;
            CP16(dK0 + dst, p); CP16(dK1 + dst, p + (size_t)32 * 2 * DIM_);
            CP16(dK0 + dst + OFF_V, p + DIM_); CP16(dK1 + dst + OFF_V, p + (size_t)32 * 2 * DIM_ + DIM_);
            if (tt + 1 >= ttA && tt + 1 < ttB) {
                const __half* pm = sM + (size_t)(tt + 1) * 64;
                uint32_t dMd = dM + dst;
                CP16(dMd, pm); CP16(dMd + 16, pm + 8); CP16(dMd + 32, pm + 16); CP16(dMd + 48, pm + 24);
            }
            CP_COMMIT();
        }

        float al[2][2];
        #pragma unroll
        for (int mfr = 0; mfr < 2; mfr++)
            #pragma unroll
            for (int hi = 0; hi < 2; hi++) {
                int lr = qg * 32 + mfr * 16 + hi * 8 + g;
                float mn = fmaxf(m[mfr][hi], fmaxf(redm[0][lr], redm[1][lr]));
                al[mfr][hi] = ex2(m[mfr][hi] - mn);
                m[mfr][hi] = mn;
            }

        // p fragments
        unsigned pf[2][2][4];
        if (mixed) {
            #pragma unroll
            for (int mfr = 0; mfr < 2; mfr++) {
                unsigned me0[4], me1[4];
                uint32_t aM = sb + stoff + mAddrB + (uint32_t)(mfr * 16 * 144);
                LDM_X4(me0, aM);
                LDM_X4(me1, aM + 32);
                #pragma unroll
                for (int j = 0; j < 4; j++) {
                    unsigned eg  = (j < 2) ? me0[(j & 1) * 2]     : me1[(j & 1) * 2];
                    unsigned eg8 = (j < 2) ? me0[(j & 1) * 2 + 1] : me1[(j & 1) * 2 + 1];
                    float2 ef0 = __half22float2(*(__half2*)&eg);
                    float2 ef1 = __half22float2(*(__half2*)&eg8);
                    float p0 = ex2(c[mfr][j][0] - m[mfr][0]) * ef0.x;
                    float p1 = ex2(c[mfr][j][1] - m[mfr][0]) * ef0.y;
                    float p2 = ex2(c[mfr][j][2] - m[mfr][1]) * ef1.x;
                    float p3 = ex2(c[mfr][j][3] - m[mfr][1]) * ef1.y;
                    pf[mfr][j >> 1][(j & 1) * 2 + 0] = h2u(__floats2half2_rn(p0, p1));
                    pf[mfr][j >> 1][(j & 1) * 2 + 1] = h2u(__floats2half2_rn(p2, p3));
                }
            }
        } else {
            float flc = (tt < ttA) ? fL : fR;
            #pragma unroll
            for (int mfr = 0; mfr < 2; mfr++) {
                float sh0 = m[mfr][0] - flc;
                float sh1 = m[mfr][1] - flc;
                #pragma unroll
                for (int j = 0; j < 4; j++) {
                    float p0 = ex2(c[mfr][j][0] - sh0);
                    float p1 = ex2(c[mfr][j][1] - sh0);
                    float p2 = ex2(c[mfr][j][2] - sh1);
                    float p3 = ex2(c[mfr][j][3] - sh1);
                    pf[mfr][j >> 1][(j & 1) * 2 + 0] = h2u(__floats2half2_rn(p0, p1));
                    pf[mfr][j >> 1][(j & 1) * 2 + 1] = h2u(__floats2half2_rn(p2, p3));
                }
            }
        }

        // rescale O (incl. row-sum accumulator n=4)
        #pragma unroll
        for (int mfr = 0; mfr < 2; mfr++)
            #pragma unroll
            for (int n = 0; n < 5; n++) {
                o[mfr][n][0] *= al[mfr][0]; o[mfr][n][1] *= al[mfr][0];
                o[mfr][n][2] *= al[mfr][1]; o[mfr][n][3] *= al[mfr][1];
            }

        // O += P.V ; row sums via constant ones-column fragment
        #pragma unroll
        for (int kc = 0; kc < 2; kc++) {
            unsigned vb0[4], vb1[4];
            uint32_t aV = sb + stoff + vAddr + (uint32_t)(kc * 16 * 80);
            LDM_X4T(vb0, aV);
            LDM_X4T(vb1, aV + 8 * 80);
            #pragma unroll
            for (int n = 0; n < 4; n++) {
                mma_f16(o[0][n], pf[0][kc], vb0[n], vb1[n]);
                mma_f16(o[1][n], pf[1][kc], vb0[n], vb1[n]);
            }
            mma_f16(o[0][4], pf[0][kc], bbone, bbone);
            mma_f16(o[1][4], pf[1][kc], bbone, bbone);
        }
    }

    __syncthreads();                   // buffers free for reuse as combine scratch

    // combine kh partials (unnormalized O + row-sums) via smem alias; stride 40
    float* Os = (float*)&KVM[0][0];
    if (kh == 1) {
        #pragma unroll
        for (int mfr = 0; mfr < 2; mfr++)
            #pragma unroll
            for (int n = 0; n < 5; n++) {
                int base0 = qg * 1280 + (mfr * 16 + g) * 40 + n * 8 + 2 * tig;
                int base1 = base0 + 8 * 40;
                float2 w0; w0.x = o[mfr][n][0]; w0.y = o[mfr][n][1];
                float2 w1; w1.x = o[mfr][n][2]; w1.y = o[mfr][n][3];
                *(float2*)&Os[base0] = w0;
                *(float2*)&Os[base1] = w1;
            }
    }
    __syncthreads();
    if (kh == 0) {
        #pragma unroll
        for (int mfr = 0; mfr < 2; mfr++) {
            #pragma unroll
            for (int n = 0; n < 4; n++) {
                int base0 = qg * 1280 + (mfr * 16 + g) * 40 + n * 8 + 2 * tig;
                int base1 = base0 + 8 * 40;
                float2 p0 = *(float2*)&Os[base0];
                float2 p1 = *(float2*)&Os[base1];
                float2 w0, w1;
                w0.x = o[mfr][n][0] + p0.x;
                w0.y = o[mfr][n][1] + p0.y;
                w1.x = o[mfr][n][2] + p1.x;
                w1.y = o[mfr][n][3] + p1.y;
                int r0 = (s * B_ + b) * LQ_ + q0 + qg * 32 + mfr * 16 + g;
                int col = h * HD_ + n * 8 + 2 * tig;
                *(float2*)&opart[(size_t)r0 * DIM_ + col] = w0;
                *(float2*)&opart[(size_t)(r0 + 8) * DIM_ + col] = w1;
            }
        }
        if (tig == 0) {
            #pragma unroll
            for (int mfr = 0; mfr < 2; mfr++) {
                int base = qg * 1280 + (mfr * 16 + g) * 40 + 32;     // n=4, tig=0 col
                float l0 = o[mfr][4][0] + Os[base];
                float l1 = o[mfr][4][2] + Os[base + 8 * 40];
                #pragma unroll
                for (int hi = 0; hi < 2; hi++) {
                    int rg = (s * B_ + b) * LQ_ + q0 + qg * 32 + mfr * 16 + hi * 8 + g;
                    float* mlb = &mlpart[(size_t)rg * (H_ * 2) + h * 2];
                    mlb[0] = m[mfr][hi];
                    mlb[1] = (hi == 0) ? l0 : l1;
                }
            }
        }
    }
}

// ---------------- split merge (m in log2 units) ----------------
__global__ void merge_kernel(const float* __restrict__ opart,
                             const float* __restrict__ mlpart,
                             float* __restrict__ ctx) {
    int idx = blockIdx.x * blockDim.x + threadIdx.x;
    int row = idx >> 6;
    int d4 = (idx & 63) * 4;
    int h = d4 >> 5;
    const float* ml0 = &mlpart[(size_t)row * (H_ * 2) + h * 2];
    const float* ml1 = ml0 + (size_t)B_ * LQ_ * H_ * 2;
    float m0 = ml0[0], l0 = ml0[1], m1 = ml1[0], l1 = ml1[1];
    float M = fmaxf(m0, m1);
    float w0 = ex2(m0 - M), w1 = ex2(m1 - M);
    float inv = 1.0f / (l0 * w0 + l1 * w1);
    float4 a = *(const float4*)&opart[(size_t)row * DIM_ + d4];
    float4 bb = *(const float4*)&opart[(size_t)(B_ * LQ_ + row) * DIM_ + d4];
    float4 r;
    r.x = (a.x * w0 + bb.x * w1) * inv;
    r.y = (a.y * w0 + bb.y * w1) * inv;
    r.z = (a.z * w0 + bb.z * w1) * inv;
    r.w = (a.w * w0 + bb.w * w1) * inv;
    *(float4*)&ctx[(size_t)row * DIM_ + d4] = r;
}

// ---------------- launch ----------------
extern "C" void kernel_launch(void* const* d_in, const int* in_sizes, int n_in,
                              void* d_out, int out_size) {
    const float* q          = (const float*)d_in[0];
    const float* kv         = (const float*)d_in[1];
    const float* in_proj_w  = (const float*)d_in[2];
    const float* in_proj_b  = (const float*)d_in[3];
    const float* out_proj_w = (const float*)d_in[4];
    const float* out_proj_b = (const float*)d_in[5];
    const float* rel_bias   = (const float*)d_in[6];
    const float* mask_scale = (const float*)d_in[7];
    float* out = (float*)d_out;

    __half *pQ, *pKV, *pEM;
    float *pC, *pOP, *pML, *pF;
    cudaGetSymbolAddress((void**)&pQ,  g_Qh);
    cudaGetSymbolAddress((void**)&pKV, g_KVh);
    cudaGetSymbolAddress((void**)&pEM, g_em);
    cudaGetSymbolAddress((void**)&pC,  g_ctx);
    cudaGetSymbolAddress((void**)&pOP, g_op);
    cudaGetSymbolAddress((void**)&pML, g_ml);
    cudaGetSymbolAddress((void**)&pF,  g_far);

    // 1/sqrt(32) * log2(e): scores in log2 domain
    const float attn_scale = 0.17677669529663687f * 1.4426950408889634f;

    emask_kernel<<<(LQ_ * T_) / 256, 256>>>(rel_bias, mask_scale, pEM, pF);

    gemm16<true><<<dim3((B_ * LQ_) / 128, DIM_ / 128), 256>>>(
        q, in_proj_w, in_proj_b, pQ, DIM_, attn_scale);

    gemm16<true><<<dim3((B_ * T_) / 128, (2 * DIM_) / 128), 256>>>(
        kv, in_proj_w + DIM_ * DIM_, in_proj_b + DIM_, pKV, 2 * DIM_, 1.0f);

    attn16<<<dim3(LQ_ / 64, H_, B_ * NSPLIT), 128>>>(pQ, pKV, pEM, pF, pOP, pML);

    merge_kernel<<<(B_ * LQ_ * DIM_ / 4) / 256, 256>>>(pOP, pML, pC);

    gemm16<false><<<dim3((B_ * LQ_) / 128, DIM_ / 128), 256>>>(
        pC, out_proj_w, out_proj_b, out, DIM_, 1.0f);
}

// round 12
// speedup vs baseline: 2.2069x; 1.1180x over previous
#include <cuda_runtime.h>
#include <cuda_fp16.h>
#include <math.h>
#include <stdint.h>

#define B_    8
#define H_    8
#define LQ_   512
#define T_    8192
#define DIM_  256
#define HD_   32
#define MAXREL_ 128
#define NSPLIT 2
#define TSPLIT (T_ / NSPLIT)
#define NTILES (TSPLIT / 64)
#define STEPF (8191.0f / 511.0f)

// ---------------- scratch ----------------
__device__ __half g_Qh[B_ * LQ_ * DIM_];
__device__ __half g_KVh[B_ * T_ * 2 * DIM_];
__device__ __half g_em[LQ_ * T_];
__device__ float  g_ctx[B_ * LQ_ * DIM_];
__device__ float  g_op[NSPLIT * B_ * LQ_ * DIM_];
__device__ float  g_ml[NSPLIT * B_ * LQ_ * H_ * 2];
__device__ float  g_far[2];

// ---------------- helpers ----------------
__device__ __forceinline__ void mma_f16(float c[4], const unsigned a[4], unsigned b0, unsigned b1) {
    asm volatile("mma.sync.aligned.m16n8k16.row.col.f32.f16.f16.f32 "
        "{%0,%1,%2,%3}, {%4,%5,%6,%7}, {%8,%9}, {%0,%1,%2,%3};"
        : "+f"(c[0]), "+f"(c[1]), "+f"(c[2]), "+f"(c[3])
        : "r"(a[0]), "r"(a[1]), "r"(a[2]), "r"(a[3]), "r"(b0), "r"(b1));
}
__device__ __forceinline__ unsigned h2u(__half2 h) { return *(unsigned*)&h; }
__device__ __forceinline__ uint32_t smem_u32(const void* p) {
    uint32_t a;
    asm("{ .reg .u64 t; cvta.to.shared.u64 t, %1; cvt.u32.u64 %0, t; }" : "=r"(a) : "l"(p));
    return a;
}
__device__ __forceinline__ float ex2(float x) {
    float r; asm("ex2.approx.f32 %0, %1;" : "=f"(r) : "f"(x)); return r;
}
#define LDM_X4(r, addr) \
    asm volatile("ldmatrix.sync.aligned.m8n8.x4.shared.b16 {%0,%1,%2,%3}, [%4];" \
        : "=r"((r)[0]), "=r"((r)[1]), "=r"((r)[2]), "=r"((r)[3]) : "r"(addr))
#define LDM_X4T(r, addr) \
    asm volatile("ldmatrix.sync.aligned.m8n8.x4.trans.shared.b16 {%0,%1,%2,%3}, [%4];" \
        : "=r"((r)[0]), "=r"((r)[1]), "=r"((r)[2]), "=r"((r)[3]) : "r"(addr))
#define CP16(dst, src) \
    asm volatile("cp.async.ca.shared.global [%0], [%1], 16;" :: "r"(dst), "l"(src))
#define CP_COMMIT() asm volatile("cp.async.commit_group;" ::: "memory")
#define CP_WAIT0()  asm volatile("cp.async.wait_group 0;" ::: "memory")

#define STG_SZ 19456
#define OFF_V  5120
#define OFF_M  10240

// ---------------- exp(mask) precompute + far constants ----------------
__global__ void emask_kernel(const float* __restrict__ rel_bias,
                             const float* __restrict__ mask_scale,
                             __half* __restrict__ em,
                             float* __restrict__ farc) {
    int idx = blockIdx.x * blockDim.x + threadIdx.x;
    int i = idx >> 13;
    int t = idx & (T_ - 1);
    float tau = (float)i * STEPF;
    float dt  = (float)t - tau;
    float dtc = fminf(fmaxf(dt, -(float)MAXREL_), (float)MAXREL_);
    int bi = (int)dtc + MAXREL_;
    float bias = rel_bias[bi];
    float z = dt * (1.0f / 64.0f);
    float lg = __logf(__expf(-0.5f * z * z) + 1e-6f);
    em[idx] = __float2half_rn(__expf(mask_scale[0] * (bias + lg)));
    if (idx == 0) {
        const float L2E = 1.4426950408889634f;
        float ms = mask_scale[0];
        farc[0] = ms * (rel_bias[0] + __logf(1e-6f)) * L2E;
        farc[1] = ms * (rel_bias[2 * MAXREL_] + __logf(1e-6f)) * L2E;
    }
}

// ---------------- fp16 GEMM (known-good) ----------------
template<bool OHALF>
__global__ void __launch_bounds__(256, 2) gemm16(const float* __restrict__ A,
                                                 const float* __restrict__ W,
                                                 const float* __restrict__ bias,
                                                 void* __restrict__ outp,
                                                 int ldo, float scale) {
    __shared__ __align__(16) unsigned As2[128][20];
    __shared__ __align__(16) unsigned Ws2[128][20];
    int tid = threadIdx.x;
    int lane = tid & 31, warp = tid >> 5;
    int wm = warp >> 1, wn = warp & 1;
    int g = lane >> 2, tig = lane & 3;
    int row0 = blockIdx.x * 128, col0 = blockIdx.y * 128;
    uint32_t sbA = smem_u32(&As2[0][0]);
    uint32_t sbW = smem_u32(&Ws2[0][0]);

    float c[2][8][4];
    #pragma unroll
    for (int i = 0; i < 2; i++)
        #pragma unroll
        for (int j = 0; j < 8; j++)
            #pragma unroll
            for (int v = 0; v < 4; v++) c[i][j][v] = 0.0f;

    int sm  = tid >> 3;
    int sk4 = (tid & 7) * 4;
    uint32_t aArow = (uint32_t)(wm * 32 + (lane & 7) + ((lane >> 3) & 1) * 8);
    uint32_t aAseg = (uint32_t)(lane >> 4);
    uint32_t aBrow = (uint32_t)(wn * 64 + (lane >> 3) * 8 + (lane & 7));

    for (int k0 = 0; k0 < 256; k0 += 32) {
        __syncthreads();
        #pragma unroll
        for (int it = 0; it < 4; it++) {
            int r = sm + it * 32;
            float4 a4 = *(const float4*)&A[(size_t)(row0 + r) * 256 + k0 + sk4];
            float4 w4 = *(const float4*)&W[(size_t)(col0 + r) * 256 + k0 + sk4];
            __half2 a01 = __floats2half2_rn(a4.x, a4.y), a23 = __floats2half2_rn(a4.z, a4.w);
            __half2 w01 = __floats2half2_rn(w4.x, w4.y), w23 = __floats2half2_rn(w4.z, w4.w);
            uint2 ua; ua.x = h2u(a01); ua.y = h2u(a23);
            uint2 uw; uw.x = h2u(w01); uw.y = h2u(w23);
            *(uint2*)&As2[r][sk4 >> 1] = ua;
            *(uint2*)&Ws2[r][sk4 >> 1] = uw;
        }
        __syncthreads();
        #pragma unroll
        for (int kc = 0; kc < 2; kc++) {
            unsigned af0[4], af1[4];
            LDM_X4(af0, sbA + aArow * 80 + (kc * 2 + aAseg) * 16);
            LDM_X4(af1, sbA + (aArow + 16) * 80 + (kc * 2 + aAseg) * 16);
            unsigned b0a[4], b1a[4], b0b[4], b1b[4];
            uint32_t aB = sbW + aBrow * 80 + kc * 32;
            LDM_X4(b0a, aB);
            LDM_X4(b1a, aB + 16);
            LDM_X4(b0b, aB + 32 * 80);
            LDM_X4(b1b, aB + 32 * 80 + 16);
            #pragma unroll
            for (int j = 0; j < 8; j++) {
                unsigned bb0 = (j < 4) ? b0a[j] : b0b[j - 4];
                unsigned bb1 = (j < 4) ? b1a[j] : b1b[j - 4];
                mma_f16(c[0][j], af0, bb0, bb1);
                mma_f16(c[1][j], af1, bb0, bb1);
            }
        }
    }

    #pragma unroll
    for (int j = 0; j < 8; j++) {
        int colg = col0 + wn * 64 + j * 8 + 2 * tig;
        float2 bv = *(const float2*)&bias[colg];
        #pragma unroll
        for (int i = 0; i < 2; i++) {
            int rowg = row0 + wm * 32 + i * 16 + g;
            float x0 = scale * (c[i][j][0] + bv.x);
            float y0 = scale * (c[i][j][1] + bv.y);
            float x1 = scale * (c[i][j][2] + bv.x);
            float y1 = scale * (c[i][j][3] + bv.y);
            if (OHALF) {
                __half* o = (__half*)outp;
                *(unsigned*)&o[(size_t)rowg * ldo + colg] = h2u(__floats2half2_rn(x0, y0));
                *(unsigned*)&o[(size_t)(rowg + 8) * ldo + colg] = h2u(__floats2half2_rn(x1, y1));
            } else {
                float* o = (float*)outp;
                float2 r0; r0.x = x0; r0.y = y0;
                float2 r1; r1.x = x1; r1.y = y1;
                *(float2*)&o[(size_t)rowg * ldo + colg] = r0;
                *(float2*)&o[(size_t)(rowg + 8) * ldo + colg] = r1;
            }
        }
    }
}

// ---------------- flash attention: independent kh softmax, 1 barrier/tile, guarded rescale ----------------
// grid (Lq/64, H, B*NSPLIT), 128 threads (4 warps). warp = (qg, kh): 32q x 32k-half.
__global__ void __launch_bounds__(128, 4) attn16(const __half* __restrict__ Qh,
                                                 const __half* __restrict__ KVh,
                                                 const __half* __restrict__ emh,
                                                 const float* __restrict__ farc,
                                                 float* __restrict__ opart,
                                                 float* __restrict__ mlpart) {
    __shared__ __align__(16) char KVM[2][STG_SZ];

    int tid = threadIdx.x;
    int lane = tid & 31, warp = tid >> 5;
    int qg = warp >> 1, kh = warp & 1;
    int g = lane >> 2, tig = lane & 3;
    int q0 = blockIdx.x * 64, h = blockIdx.y;
    int b = blockIdx.z >> 1, s = blockIdx.z & 1;
    int tb = s * TSPLIT;
    uint32_t sb = smem_u32(&KVM[0][0]);

    // far/mixed tile band
    float tauMin = (float)q0 * STEPF;
    float tauMax = (float)(q0 + 63) * STEPF;
    int ttA = (int)floorf((tauMin - 448.0f - 63.0f - (float)tb) * (1.0f / 64.0f)) + 1;
    int ttB = (int)ceilf((tauMax + 448.0f - (float)tb) * (1.0f / 64.0f));
    ttA = max(0, min(NTILES, ttA));
    ttB = max(ttA, min(NTILES, ttB));
    float fL = farc[0], fR = farc[1];

    // Q A-frags resident
    unsigned qf[2][2][4];
    #pragma unroll
    for (int mfr = 0; mfr < 2; mfr++) {
        const __half* qb0 = &Qh[(size_t)(b * LQ_ + q0 + qg * 32 + mfr * 16 + g) * DIM_ + h * HD_ + 2 * tig];
        #pragma unroll
        for (int kc = 0; kc < 2; kc++) {
            const __half* qb = qb0 + kc * 16;
            qf[mfr][kc][0] = *(const unsigned*)qb;
            qf[mfr][kc][1] = *(const unsigned*)(qb + 8 * DIM_);
            qf[mfr][kc][2] = *(const unsigned*)(qb + 8);
            qf[mfr][kc][3] = *(const unsigned*)(qb + 8 * DIM_ + 8);
        }
    }

    // staging addresses
    int srow = tid >> 2, seg = tid & 3;
    uint32_t dK0 = sb + (uint32_t)(srow * 80 + seg * 16);
    uint32_t dK1 = dK0 + 32 * 80;
    const __half* sKV = &KVh[(size_t)(b * T_ + tb + srow) * (2 * DIM_) + h * HD_ + seg * 8];
    int mrow = tid >> 1, mseg = (tid & 1) * 64;
    uint32_t dM = sb + OFF_M + (uint32_t)(mrow * 144 + mseg);
    const __half* sM = &emh[(size_t)(q0 + mrow) * T_ + tb + mseg / 2];

    // fragment lane addresses
    uint32_t kAddr = (uint32_t)((kh * 32 + (lane >> 3) * 8 + (lane & 7)) * 80);
    uint32_t vAddr = (uint32_t)(OFF_V + (kh * 32 + (lane & 7)) * 80 + (lane >> 3) * 16);
    uint32_t mAddrB = (uint32_t)(OFF_M + (qg * 32 + (lane & 15)) * 144 + kh * 64 + (lane >> 4) * 16);

    // ones-column B fragment (row-sum trick)
    unsigned bbone = (g == 0) ? 0x3C003C00u : 0u;

    float m[2][2], o[2][5][4];
    #pragma unroll
    for (int i = 0; i < 2; i++)
        #pragma unroll
        for (int j = 0; j < 2; j++) m[i][j] = -1e30f;
    #pragma unroll
    for (int i = 0; i < 2; i++)
        #pragma unroll
        for (int n = 0; n < 5; n++)
            #pragma unroll
            for (int v = 0; v < 4; v++) o[i][n][v] = 0.0f;

    // prologue: stage tile 0 into buffer 0
    {
        const __half* p = sKV;
        CP16(dK0, p); CP16(dK1, p + (size_t)32 * 2 * DIM_);
        CP16(dK0 + OFF_V, p + DIM_); CP16(dK1 + OFF_V, p + (size_t)32 * 2 * DIM_ + DIM_);
        if (0 >= ttA && 0 < ttB) {
            const __half* pm = sM;
            CP16(dM, pm); CP16(dM + 16, pm + 8); CP16(dM + 32, pm + 16); CP16(dM + 48, pm + 24);
        }
        CP_COMMIT();
    }

    for (int tt = 0; tt < NTILES; tt++) {
        uint32_t stoff = (uint32_t)((tt & 1) * STG_SZ);
        bool mixed = (tt >= ttA) && (tt < ttB);
        CP_WAIT0();
        __syncthreads();               // tile tt staged by all threads; buf other fully consumed

        // prefetch tile tt+1 immediately (other buffer last read in tile tt-1)
        if (tt + 1 < NTILES) {
            uint32_t dst = (uint32_t)(((tt & 1) ^ 1) * STG_SZ);
            const __half* p = sKV + (size_t)(tt + 1) * 64 * 2 * DIM_;
            CP16(dK0 + dst, p); CP16(dK1 + dst, p + (size_t)32 * 2 * DIM_);
            CP16(dK0 + dst + OFF_V, p + DIM_); CP16(dK1 + dst + OFF_V, p + (size_t)32 * 2 * DIM_ + DIM_);
            if (tt + 1 >= ttA && tt + 1 < ttB) {
                const __half* pm = sM + (size_t)(tt + 1) * 64;
                uint32_t dMd = dM + dst;
                CP16(dMd, pm); CP16(dMd + 16, pm + 8); CP16(dMd + 32, pm + 16); CP16(dMd + 48, pm + 24);
            }
            CP_COMMIT();
        }

        // S = Q.K^T (32q x 32k per warp)
        float c[2][4][4];
        #pragma unroll
        for (int mfr = 0; mfr < 2; mfr++)
            #pragma unroll
            for (int j = 0; j < 4; j++)
                #pragma unroll
                for (int v = 0; v < 4; v++) c[mfr][j][v] = 0.0f;
        #pragma unroll
        for (int kc = 0; kc < 2; kc++) {
            unsigned kb0[4], kb1[4];
            uint32_t aB = sb + stoff + kAddr + kc * 32;
            LDM_X4(kb0, aB);
            LDM_X4(kb1, aB + 16);
            #pragma unroll
            for (int j = 0; j < 4; j++) {
                mma_f16(c[0][j], qf[0][kc], kb0[j], kb1[j]);
                mma_f16(c[1][j], qf[1][kc], kb0[j], kb1[j]);
            }
        }

        // per-warp row max over own 32 cols (quad shuffles only)
        float mold[2][2];
        bool upd = false;
        #pragma unroll
        for (int mfr = 0; mfr < 2; mfr++)
            #pragma unroll
            for (int hi = 0; hi < 2; hi++) {
                float mx = fmaxf(c[mfr][0][hi * 2], c[mfr][0][hi * 2 + 1]);
                #pragma unroll
                for (int j = 1; j < 4; j++)
                    mx = fmaxf(mx, fmaxf(c[mfr][j][hi * 2], c[mfr][j][hi * 2 + 1]));
                mx = fmaxf(mx, __shfl_xor_sync(0xffffffffu, mx, 1));
                mx = fmaxf(mx, __shfl_xor_sync(0xffffffffu, mx, 2));
                mold[mfr][hi] = m[mfr][hi];
                float mn = fmaxf(m[mfr][hi], mx);
                upd |= (mn > m[mfr][hi]);
                m[mfr][hi] = mn;
            }

        // rescale O only when some row's max moved (warp-uniform guard)
        if (__ballot_sync(0xffffffffu, upd)) {
            #pragma unroll
            for (int mfr = 0; mfr < 2; mfr++) {
                float a0 = ex2(mold[mfr][0] - m[mfr][0]);
                float a1 = ex2(mold[mfr][1] - m[mfr][1]);
                #pragma unroll
                for (int n = 0; n < 5; n++) {
                    o[mfr][n][0] *= a0; o[mfr][n][1] *= a0;
                    o[mfr][n][2] *= a1; o[mfr][n][3] *= a1;
                }
            }
        }

        // p fragments
        unsigned pf[2][2][4];
        if (mixed) {
            #pragma unroll
            for (int mfr = 0; mfr < 2; mfr++) {
                unsigned me0[4], me1[4];
                uint32_t aM = sb + stoff + mAddrB + (uint32_t)(mfr * 16 * 144);
                LDM_X4(me0, aM);
                LDM_X4(me1, aM + 32);
                #pragma unroll
                for (int j = 0; j < 4; j++) {
                    unsigned eg  = (j < 2) ? me0[(j & 1) * 2]     : me1[(j & 1) * 2];
                    unsigned eg8 = (j < 2) ? me0[(j & 1) * 2 + 1] : me1[(j & 1) * 2 + 1];
                    float2 ef0 = __half22float2(*(__half2*)&eg);
                    float2 ef1 = __half22float2(*(__half2*)&eg8);
                    float p0 = ex2(c[mfr][j][0] - m[mfr][0]) * ef0.x;
                    float p1 = ex2(c[mfr][j][1] - m[mfr][0]) * ef0.y;
                    float p2 = ex2(c[mfr][j][2] - m[mfr][1]) * ef1.x;
                    float p3 = ex2(c[mfr][j][3] - m[mfr][1]) * ef1.y;
                    pf[mfr][j >> 1][(j & 1) * 2 + 0] = h2u(__floats2half2_rn(p0, p1));
                    pf[mfr][j >> 1][(j & 1) * 2 + 1] = h2u(__floats2half2_rn(p2, p3));
                }
            }
        } else {
            float flc = (tt < ttA) ? fL : fR;
            #pragma unroll
            for (int mfr = 0; mfr < 2; mfr++) {
                float sh0 = m[mfr][0] - flc;
                float sh1 = m[mfr][1] - flc;
                #pragma unroll
                for (int j = 0; j < 4; j++) {
                    float p0 = ex2(c[mfr][j][0] - sh0);
                    float p1 = ex2(c[mfr][j][1] - sh0);
                    float p2 = ex2(c[mfr][j][2] - sh1);
                    float p3 = ex2(c[mfr][j][3] - sh1);
                    pf[mfr][j >> 1][(j & 1) * 2 + 0] = h2u(__floats2half2_rn(p0, p1));
                    pf[mfr][j >> 1][(j & 1) * 2 + 1] = h2u(__floats2half2_rn(p2, p3));
                }
            }
        }

        // O += P.V ; row sums via constant ones-column fragment
        #pragma unroll
        for (int kc = 0; kc < 2; kc++) {
            unsigned vb0[4], vb1[4];
            uint32_t aV = sb + stoff + vAddr + (uint32_t)(kc * 16 * 80);
            LDM_X4T(vb0, aV);
            LDM_X4T(vb1, aV + 8 * 80);
            #pragma unroll
            for (int n = 0; n < 4; n++) {
                mma_f16(o[0][n], pf[0][kc], vb0[n], vb1[n]);
                mma_f16(o[1][n], pf[1][kc], vb0[n], vb1[n]);
            }
            mma_f16(o[0][4], pf[0][kc], bbone, bbone);
            mma_f16(o[1][4], pf[1][kc], bbone, bbone);
        }
    }

    __syncthreads();                   // buffers free for combine scratch

    // combine kh halves with alpha weights (stride 42 floats/row; m at col 40)
    float* Os = (float*)&KVM[0][0];
    if (kh == 1) {
        #pragma unroll
        for (int mfr = 0; mfr < 2; mfr++) {
            int r0 = qg * 1344 + (mfr * 16 + g) * 42;
            int r1 = r0 + 8 * 42;
            #pragma unroll
            for (int n = 0; n < 5; n++) {
                float2 w0; w0.x = o[mfr][n][0]; w0.y = o[mfr][n][1];
                float2 w1; w1.x = o[mfr][n][2]; w1.y = o[mfr][n][3];
                *(float2*)&Os[r0 + n * 8 + 2 * tig] = w0;
                *(float2*)&Os[r1 + n * 8 + 2 * tig] = w1;
            }
            if (tig == 0) {
                Os[r0 + 40] = m[mfr][0];
                Os[r1 + 40] = m[mfr][1];
            }
        }
    }
    __syncthreads();
    if (kh == 0) {
        #pragma unroll
        for (int mfr = 0; mfr < 2; mfr++) {
            int r0 = qg * 1344 + (mfr * 16 + g) * 42;
            int r1 = r0 + 8 * 42;
            float mo0 = Os[r0 + 40], mo1 = Os[r1 + 40];
            float M0 = fmaxf(m[mfr][0], mo0);
            float M1 = fmaxf(m[mfr][1], mo1);
            float ws0 = ex2(m[mfr][0] - M0), wo0 = ex2(mo0 - M0);
            float ws1 = ex2(m[mfr][1] - M1), wo1 = ex2(mo1 - M1);
            #pragma unroll
            for (int n = 0; n < 4; n++) {
                float2 p0 = *(float2*)&Os[r0 + n * 8 + 2 * tig];
                float2 p1 = *(float2*)&Os[r1 + n * 8 + 2 * tig];
                float2 w0, w1;
                w0.x = o[mfr][n][0] * ws0 + p0.x * wo0;
                w0.y = o[mfr][n][1] * ws0 + p0.y * wo0;
                w1.x = o[mfr][n][2] * ws1 + p1.x * wo1;
                w1.y = o[mfr][n][3] * ws1 + p1.y * wo1;
                int rg = (s * B_ + b) * LQ_ + q0 + qg * 32 + mfr * 16 + g;
                int col = h * HD_ + n * 8 + 2 * tig;
                *(float2*)&opart[(size_t)rg * DIM_ + col] = w0;
                *(float2*)&opart[(size_t)(rg + 8) * DIM_ + col] = w1;
            }
            if (tig == 0) {
                float l0 = o[mfr][4][0] * ws0 + Os[r0 + 32] * wo0;
                float l1 = o[mfr][4][2] * ws1 + Os[r1 + 32] * wo1;
                int rg = (s * B_ + b) * LQ_ + q0 + qg * 32 + mfr * 16 + g;
                float* mlb0 = &mlpart[(size_t)rg * (H_ * 2) + h * 2];
                float* mlb1 = &mlpart[(size_t)(rg + 8) * (H_ * 2) + h * 2];
                mlb0[0] = M0; mlb0[1] = l0;
                mlb1[0] = M1; mlb1[1] = l1;
            }
        }
    }
}

// ---------------- split merge (m in log2 units) ----------------
__global__ void merge_kernel(const float* __restrict__ opart,
                             const float* __restrict__ mlpart,
                             float* __restrict__ ctx) {
    int idx = blockIdx.x * blockDim.x + threadIdx.x;
    int row = idx >> 6;
    int d4 = (idx & 63) * 4;
    int h = d4 >> 5;
    const float* ml0 = &mlpart[(size_t)row * (H_ * 2) + h * 2];
    const float* ml1 = ml0 + (size_t)B_ * LQ_ * H_ * 2;
    float m0 = ml0[0], l0 = ml0[1], m1 = ml1[0], l1 = ml1[1];
    float M = fmaxf(m0, m1);
    float w0 = ex2(m0 - M), w1 = ex2(m1 - M);
    float inv = 1.0f / (l0 * w0 + l1 * w1);
    float4 a = *(const float4*)&opart[(size_t)row * DIM_ + d4];
    float4 bb = *(const float4*)&opart[(size_t)(B_ * LQ_ + row) * DIM_ + d4];
    float4 r;
    r.x = (a.x * w0 + bb.x * w1) * inv;
    r.y = (a.y * w0 + bb.y * w1) * inv;
    r.z = (a.z * w0 + bb.z * w1) * inv;
    r.w = (a.w * w0 + bb.w * w1) * inv;
    *(float4*)&ctx[(size_t)row * DIM_ + d4] = r;
}

// ---------------- launch ----------------
extern "C" void kernel_launch(void* const* d_in, const int* in_sizes, int n_in,
                              void* d_out, int out_size) {
    const float* q          = (const float*)d_in[0];
    const float* kv         = (const float*)d_in[1];
    const float* in_proj_w  = (const float*)d_in[2];
    const float* in_proj_b  = (const float*)d_in[3];
    const float* out_proj_w = (const float*)d_in[4];
    const float* out_proj_b = (const float*)d_in[5];
    const float* rel_bias   = (const float*)d_in[6];
    const float* mask_scale = (const float*)d_in[7];
    float* out = (float*)d_out;

    __half *pQ, *pKV, *pEM;
    float *pC, *pOP, *pML, *pF;
    cudaGetSymbolAddress((void**)&pQ,  g_Qh);
    cudaGetSymbolAddress((void**)&pKV, g_KVh);
    cudaGetSymbolAddress((void**)&pEM, g_em);
    cudaGetSymbolAddress((void**)&pC,  g_ctx);
    cudaGetSymbolAddress((void**)&pOP, g_op);
    cudaGetSymbolAddress((void**)&pML, g_ml);
    cudaGetSymbolAddress((void**)&pF,  g_far);

    const float attn_scale = 0.17677669529663687f * 1.4426950408889634f;

    emask_kernel<<<(LQ_ * T_) / 256, 256>>>(rel_bias, mask_scale, pEM, pF);

    gemm16<true><<<dim3((B_ * LQ_) / 128, DIM_ / 128), 256>>>(
        q, in_proj_w, in_proj_b, pQ, DIM_, attn_scale);

    gemm16<true><<<dim3((B_ * T_) / 128, (2 * DIM_) / 128), 256>>>(
        kv, in_proj_w + DIM_ * DIM_, in_proj_b + DIM_, pKV, 2 * DIM_, 1.0f);

    attn16<<<dim3(LQ_ / 64, H_, B_ * NSPLIT), 128>>>(pQ, pKV, pEM, pF, pOP, pML);

    merge_kernel<<<(B_ * LQ_ * DIM_ / 4) / 256, 256>>>(pOP, pML, pC);

    gemm16<false><<<dim3((B_ * LQ_) / 128, DIM_ / 128), 256>>>(
        pC, out_proj_w, out_proj_b, out, DIM_, 1.0f);
}